// round 1
// baseline (speedup 1.0000x reference)
#include <cuda_runtime.h>
#include <cuda_bf16.h>

// KAN 3x3 convolution, x in [0,1), uniform cubic B-spline grid (G=5, s=3, h=0.4).
// Per kernel position p and active knot interval k (0..2 for x in [0,1)),
// the spline contribution is a single cubic in local param t:
//   f = ((c3*t + c2)*t + c1)*t + c0
// with coefficients derived from spline_weight[p, k+2 .. k+5].

#define OUT_H 254
#define OUT_W 254
#define IN_W  256
#define TW 32
#define TH 8
#define IW (TW + 2)   // 34
#define IH (TH + 2)   // 10
#define PADW 35       // padded float2 row stride

__global__ __launch_bounds__(256)
void kan_conv_kernel(const float* __restrict__ x,
                     const float* __restrict__ bw,
                     const float* __restrict__ sw,
                     float* __restrict__ out)
{
    __shared__ float2 s_pix[IH][PADW];   // (u, silu) per input pixel
    __shared__ float4 s_coef[27];        // [p*3 + k] cubic coeffs
    __shared__ float  s_bw[9];

    const int tx  = threadIdx.x;   // 0..31
    const int ty  = threadIdx.y;   // 0..7
    const int tid = ty * 32 + tx;
    const int b   = blockIdx.z;
    const int ox0 = blockIdx.x * TW;
    const int oy0 = blockIdx.y * TH;

    // ---- stage cubic coefficient table (27 float4) from spline_weight ----
    if (tid < 27) {
        const int p = tid / 3;
        const int k = tid - 3 * p;
        const float* w = sw + p * 8 + (k + 2);
        const float w0 = __ldg(w + 0);
        const float w1 = __ldg(w + 1);
        const float w2 = __ldg(w + 2);
        const float w3 = __ldg(w + 3);
        float4 c;
        c.x = (w0 + 4.0f * w1 + w2) * (1.0f / 6.0f);
        c.y = (w2 - w0) * 0.5f;
        c.z = (w0 - 2.0f * w1 + w2) * 0.5f;
        c.w = (3.0f * (w1 - w2) + (w3 - w0)) * (1.0f / 6.0f);
        s_coef[tid] = c;
    }
    if (tid >= 32 && tid < 41) s_bw[tid - 32] = __ldg(bw + (tid - 32));

    // ---- stage input tile: per-pixel u = 2.5x+0.5 and silu(x) ----
    const float* xb = x + (size_t)b * (IN_W * IN_W);
    #pragma unroll
    for (int idx = tid; idx < IW * IH; idx += 256) {
        const int r = idx / IW;
        const int c = idx - r * IW;
        const int gy = min(oy0 + r, IN_W - 1);
        const int gx = min(ox0 + c, IN_W - 1);
        const float v = __ldg(xb + gy * IN_W + gx);
        const float u = 2.5f * v + 0.5f;
        const float e = __expf(-v);
        const float sil = __fdividef(v, 1.0f + e);
        s_pix[r][c] = make_float2(u, sil);
    }
    __syncthreads();

    const int ox = ox0 + tx;
    const int oy = oy0 + ty;
    if (ox >= OUT_W || oy >= OUT_H) return;

    // base_weight into registers (one broadcast LDS each, amortized)
    float bwr[9];
    #pragma unroll
    for (int p = 0; p < 9; p++) bwr[p] = s_bw[p];

    float acc = 0.0f;
    #pragma unroll
    for (int dy = 0; dy < 3; dy++) {
        #pragma unroll
        for (int dx = 0; dx < 3; dx++) {
            const int p = dy * 3 + dx;
            const float2 pv = s_pix[ty + dy][tx + dx];
            const float fk = floorf(pv.x);
            int k = (int)fk;
            k = max(0, min(k, 2));
            const float t = pv.x - fk;
            const float4 c = s_coef[p * 3 + k];
            float r = fmaf(c.w, t, c.z);
            r = fmaf(r, t, c.y);
            r = fmaf(r, t, c.x);
            acc += r;
            acc = fmaf(pv.y, bwr[p], acc);
        }
    }

    out[(size_t)b * (OUT_H * OUT_W) + oy * OUT_W + ox] = acc;
}

extern "C" void kernel_launch(void* const* d_in, const int* in_sizes, int n_in,
                              void* d_out, int out_size) {
    const float* x  = (const float*)d_in[0];
    const float* bw = (const float*)d_in[1];
    const float* sw = (const float*)d_in[2];
    float* out = (float*)d_out;

    dim3 block(32, 8, 1);
    dim3 grid((OUT_W + TW - 1) / TW,   // 8
              (OUT_H + TH - 1) / TH,   // 32
              32);                     // batch
    kan_conv_kernel<<<grid, block>>>(x, bw, sw, out);
}